// round 15
// baseline (speedup 1.0000x reference)
#include <cuda_runtime.h>
#include <math.h>

#define FF 15
#define HH 128
#define LL 12
#define NBINS 16
#define MM 47            // 3*NB - 1
#define OUTW (FF*MM)     // 705
#define FP 48            // padded per-feature width
#define NFP 16           // padded feature count
#define OUTWP (NFP*FP)   // 768
#define TAILV 3.0f
#define MINW 0.001f
#define MINH 0.001f
#define MIND 0.001f
#define SPB 64           // samples per block
#define TL 132           // row stride for h/t buffers
#define XL 16            // row stride for x buffer
#define NT 128           // threads per CTA
#define NROW 8           // rows per thread
#define RSTRIDE 8        // row-group count (row = rx + RSTRIDE*i)
#define OSTRIDE 54       // out-head warp-scratch row stride (EVEN: float2-safe)

typedef unsigned long long ull;

// Hidden units permuted sorted-by-degree (exact similarity transform).
__host__ __device__ __forceinline__ int cumcnt(int d)
{
    return (d <= 2) ? 10 * d : 9 * d + 2;
}
__host__ __device__ __forceinline__ int degnew(int j)
{
    return (j < 20) ? (j / 10 + 1) : ((j - 2) / 9 + 1);
}
__host__ __device__ __forceinline__ int permj(int j)
{
    int d = degnew(j);
    int t = j - cumcnt(d - 1);
    return (d - 1) + 14 * t;
}
__host__ __device__ __forceinline__ int r4(int x) { return (x + 3) & ~3; }
__host__ __device__ __forceinline__ int kresg(int g)
{
    return r4(cumcnt(degnew(8 * g + 7)));
}

// Balanced warp->features map for the out head (sum of kout ~equal per warp)
__device__ const signed char FEAT[4][4] = {
    {14, 9, 3, 0}, {13, 10, 4, -1}, {12, 11, 2, 1}, {8, 7, 6, 5}
};

// Pre-masked, transposed, permuted, padded weights (scratch)
// g_Wi: k-axis PRE-FLIPPED for even layers (virtual feature reversal)
__device__ float g_Wi[LL * 16 * HH];        // [l][k'(16)][j']
__device__ float g_Wr[LL * 4 * HH * HH];    // [l][blk*2+sub][k'][j']
__device__ float g_Wo[LL * HH * OUTWP];     // [l][k'][f*48+m]
__device__ float g_bo[LL * OUTWP];          // padded out bias
__device__ float g_bi[LL * HH];             // permuted init bias
__device__ float g_br[LL * 4 * HH];         // permuted res bias

// ---------------------------------------------------------------------------
__global__ void prep_kernel(const float* __restrict__ Wi,
                            const float* __restrict__ bi,
                            const float* __restrict__ Wr,
                            const float* __restrict__ br,
                            const float* __restrict__ Wo,
                            const float* __restrict__ bo)
{
    const int n1 = LL * 16 * HH;
    const int n2 = LL * 4 * HH * HH;
    const int n3 = LL * HH * OUTWP;
    const int n4 = LL * OUTWP;
    const int n5 = LL * HH;
    const int n6 = LL * 4 * HH;
    const int ntot = n1 + n2 + n3 + n4 + n5 + n6;
    for (int i = blockIdx.x * blockDim.x + threadIdx.x; i < ntot;
         i += gridDim.x * blockDim.x) {
        if (i < n1) {
            int j = i % HH;               // hidden (permuted) index
            int k = (i / HH) % 16;        // PHYSICAL xs slot
            int l = i / (16 * HH);
            // even layers: logical feature = 14-k (virtual reversal)
            int klog = ((l & 1) == 0) ? (14 - k) : k;
            float v = 0.f;
            if (klog >= 0 && klog < FF) {
                int oj = permj(j);
                if (degnew(j) >= klog + 1) v = Wi[(l * HH + oj) * FF + klog];
            }
            g_Wi[i] = v;
        } else if (i < n1 + n2) {
            int t = i - n1;
            int j = t % HH;
            int k = (t / HH) % HH;
            int m = t / (HH * HH);
            float v = 0.f;
            if (degnew(j) >= degnew(k))
                v = Wr[(m * HH + permj(j)) * HH + permj(k)];
            g_Wr[t] = v;
        } else if (i < n1 + n2 + n3) {
            int t = i - n1 - n2;
            int c = t % OUTWP;
            int k = (t / OUTWP) % HH;
            int l = t / (HH * OUTWP);
            int f = c / FP, m = c % FP;
            float v = 0.f;
            if (f < FF && m < MM) {
                if (f + 1 > degnew(k))
                    v = Wo[(l * OUTW + f * MM + m) * HH + permj(k)];
            }
            g_Wo[t] = v;
        } else if (i < n1 + n2 + n3 + n4) {
            int t = i - n1 - n2 - n3;
            int c = t % OUTWP;
            int l = t / OUTWP;
            int f = c / FP, m = c % FP;
            g_bo[t] = (f < FF && m < MM) ? bo[l * OUTW + f * MM + m] : 0.f;
        } else if (i < n1 + n2 + n3 + n4 + n5) {
            int t = i - n1 - n2 - n3 - n4;
            int j = t % HH;
            int l = t / HH;
            g_bi[t] = bi[l * HH + permj(j)];
        } else {
            int t = i - n1 - n2 - n3 - n4 - n5;
            int j = t % HH;
            int m = t / HH;
            g_br[t] = br[m * HH + permj(j)];
        }
    }
}

// ---------------------------------------------------------------------------
__device__ __forceinline__ void fma2(ull& d, ull a, ull b)
{
    asm("fma.rn.f32x2 %0, %1, %2, %0;" : "+l"(d) : "l"(a), "l"(b));
}
__device__ __forceinline__ ull pack2(float v)
{
    ull r; asm("mov.b64 %0, {%1, %1};" : "=l"(r) : "f"(v)); return r;
}
__device__ __forceinline__ ull packf2(float a, float b)
{
    ull r; asm("mov.b64 %0, {%1, %2};" : "=l"(r) : "f"(a), "f"(b)); return r;
}

// ---------------------------------------------------------------------------
// Loop-2 helpers (high columns only, 4 cols = 2 f32x2 pairs)
__device__ __forceinline__ void loadW2(ull (&w)[4][2],
                                       const float* __restrict__ Wg,
                                       int wld, int c0hi, int k0)
{
#pragma unroll
    for (int kk = 0; kk < 4; kk++) {
        ulonglong2 hi = __ldg((const ulonglong2*)(Wg + (k0 + kk) * wld + c0hi));
        w[kk][0] = hi.x; w[kk][1] = hi.y;
    }
}

template <bool RELU>
__device__ __forceinline__ void computeHigh(ull (&acc)[NROW][4],
                                            const float* __restrict__ As,
                                            int ald, int rx, int k0,
                                            const ull (&w)[4][2])
{
#pragma unroll
    for (int i = 0; i < NROW; i++) {
        float4 a = *(const float4*)&As[(rx + RSTRIDE * i) * ald + k0];
        if (RELU) {
            a.x = fmaxf(a.x, 0.f); a.y = fmaxf(a.y, 0.f);
            a.z = fmaxf(a.z, 0.f); a.w = fmaxf(a.w, 0.f);
        }
        ull a0 = pack2(a.x), a1 = pack2(a.y), a2 = pack2(a.z), a3 = pack2(a.w);
        fma2(acc[i][2], a0, w[0][0]); fma2(acc[i][3], a0, w[0][1]);
        fma2(acc[i][2], a1, w[1][0]); fma2(acc[i][3], a1, w[1][1]);
        fma2(acc[i][2], a2, w[2][0]); fma2(acc[i][3], a2, w[2][1]);
        fma2(acc[i][2], a3, w[3][0]); fma2(acc[i][3], a3, w[3][1]);
    }
}

// ---------------------------------------------------------------------------
// Paired GEMM (init/res): thread covers 4 low cols + 4 high cols.
// Loop1 (k < kl): all 8 cols. Loop2 (kl <= k < kh): high cols only,
// double-buffered weight loads. kl, kh multiples of 4, warp-uniform.
// ---------------------------------------------------------------------------
template <bool RELU, bool ACC>
__device__ __forceinline__ void gemm2p(const float* __restrict__ As, int ald,
                                       const float* __restrict__ Wg, int wld,
                                       const float* __restrict__ bias,
                                       float* __restrict__ Cs, int cld,
                                       int rx, int c0lo, int c0hi,
                                       int kl, int kh)
{
    ull acc[NROW][4];
    {
        float2 b0 = *(const float2*)&bias[c0lo];
        float2 b1 = *(const float2*)&bias[c0lo + 2];
        float2 b2 = *(const float2*)&bias[c0hi];
        float2 b3 = *(const float2*)&bias[c0hi + 2];
#pragma unroll
        for (int i = 0; i < NROW; i++) {
            float2 p0 = make_float2(0.f, 0.f), p1 = p0, p2 = p0, p3 = p0;
            if (ACC) {
                const float* cr = &Cs[(rx + RSTRIDE * i) * cld];
                p0 = *(const float2*)&cr[c0lo];
                p1 = *(const float2*)&cr[c0lo + 2];
                p2 = *(const float2*)&cr[c0hi];
                p3 = *(const float2*)&cr[c0hi + 2];
            }
            acc[i][0] = packf2(b0.x + p0.x, b0.y + p0.y);
            acc[i][1] = packf2(b1.x + p1.x, b1.y + p1.y);
            acc[i][2] = packf2(b2.x + p2.x, b2.y + p2.y);
            acc[i][3] = packf2(b3.x + p3.x, b3.y + p3.y);
        }
    }

#pragma unroll 1
    for (int k0 = 0; k0 < kl; k0 += 4) {
        ull w[4][4];
#pragma unroll
        for (int kk = 0; kk < 4; kk++) {
            const float* wr = Wg + (k0 + kk) * wld;
            ulonglong2 lo = __ldg((const ulonglong2*)(wr + c0lo));
            ulonglong2 hi = __ldg((const ulonglong2*)(wr + c0hi));
            w[kk][0] = lo.x; w[kk][1] = lo.y;
            w[kk][2] = hi.x; w[kk][3] = hi.y;
        }
#pragma unroll
        for (int i = 0; i < NROW; i++) {
            float4 a = *(const float4*)&As[(rx + RSTRIDE * i) * ald + k0];
            if (RELU) {
                a.x = fmaxf(a.x, 0.f); a.y = fmaxf(a.y, 0.f);
                a.z = fmaxf(a.z, 0.f); a.w = fmaxf(a.w, 0.f);
            }
            ull a0 = pack2(a.x), a1 = pack2(a.y), a2 = pack2(a.z), a3 = pack2(a.w);
#pragma unroll
            for (int j = 0; j < 4; j++) fma2(acc[i][j], a0, w[0][j]);
#pragma unroll
            for (int j = 0; j < 4; j++) fma2(acc[i][j], a1, w[1][j]);
#pragma unroll
            for (int j = 0; j < 4; j++) fma2(acc[i][j], a2, w[2][j]);
#pragma unroll
            for (int j = 0; j < 4; j++) fma2(acc[i][j], a3, w[3][j]);
        }
    }

    // Loop2: double-buffered (hide L2 weight latency)
    if (kl < kh) {
        ull wA[4][2], wB[4][2];
        loadW2(wA, Wg, wld, c0hi, kl);
#pragma unroll 1
        for (int k0 = kl; k0 < kh; k0 += 8) {
            bool has2 = (k0 + 4) < kh;
            if (has2) loadW2(wB, Wg, wld, c0hi, k0 + 4);
            computeHigh<RELU>(acc, As, ald, rx, k0, wA);
            if (k0 + 8 < kh) loadW2(wA, Wg, wld, c0hi, k0 + 8);
            if (has2) computeHigh<RELU>(acc, As, ald, rx, k0 + 4, wB);
        }
    }

#pragma unroll
    for (int i = 0; i < NROW; i++) {
        float* cr = &Cs[(rx + RSTRIDE * i) * cld];
        *(float2*)&cr[c0lo]     = *(float2*)&acc[i][0];
        *(float2*)&cr[c0lo + 2] = *(float2*)&acc[i][1];
        *(float2*)&cr[c0hi]     = *(float2*)&acc[i][2];
        *(float2*)&cr[c0hi + 2] = *(float2*)&acc[i][3];
    }
}

// ---------------------------------------------------------------------------
// Out-head GEMM helpers (6 cols = 3 f32x2 pairs), double-buffered.
__device__ __forceinline__ void loadWo(ull (&w)[4][3],
                                       const float* __restrict__ Wg,
                                       int c0w, int k0)
{
#pragma unroll
    for (int kk = 0; kk < 4; kk++) {
        const float* wr = Wg + (k0 + kk) * OUTWP + c0w;
        w[kk][0] = __ldg((const ull*)(wr));
        w[kk][1] = __ldg((const ull*)(wr + 2));
        w[kk][2] = __ldg((const ull*)(wr + 4));
    }
}

__device__ __forceinline__ void computeO(ull (&acc)[8][3],
                                         const float* __restrict__ As,
                                         int half, int rxw, int k0,
                                         const ull (&w)[4][3])
{
#pragma unroll
    for (int i = 0; i < 8; i++) {
        float4 a = *(const float4*)&As[(32 * half + rxw + 4 * i) * TL + k0];
        ull a0 = pack2(a.x), a1 = pack2(a.y), a2 = pack2(a.z), a3 = pack2(a.w);
#pragma unroll
        for (int j = 0; j < 3; j++) fma2(acc[i][j], a0, w[0][j]);
#pragma unroll
        for (int j = 0; j < 3; j++) fma2(acc[i][j], a1, w[1][j]);
#pragma unroll
        for (int j = 0; j < 3; j++) fma2(acc[i][j], a2, w[2][j]);
#pragma unroll
        for (int j = 0; j < 3; j++) fma2(acc[i][j], a3, w[3][j]);
    }
}

// Out-head GEMM for one (feature, 32-sample half), warp-private.
__device__ __forceinline__ void gemm_out(const float* __restrict__ As,
                                         const float* __restrict__ Wg,
                                         const float* __restrict__ bias,
                                         float* __restrict__ ws,
                                         int half, int rxw, int colsub,
                                         int c0w, int kend)
{
    ull acc[8][3];
    {
        float2 b0 = *(const float2*)&bias[c0w];
        float2 b1 = *(const float2*)&bias[c0w + 2];
        float2 b2 = *(const float2*)&bias[c0w + 4];
#pragma unroll
        for (int i = 0; i < 8; i++) {
            acc[i][0] = packf2(b0.x, b0.y);
            acc[i][1] = packf2(b1.x, b1.y);
            acc[i][2] = packf2(b2.x, b2.y);
        }
    }

    if (kend > 0) {
        ull wA[4][3], wB[4][3];
        loadWo(wA, Wg, c0w, 0);
#pragma unroll 1
        for (int k0 = 0; k0 < kend; k0 += 8) {
            bool has2 = (k0 + 4) < kend;
            if (has2) loadWo(wB, Wg, c0w, k0 + 4);
            computeO(acc, As, half, rxw, k0, wA);
            if (k0 + 8 < kend) loadWo(wA, Wg, c0w, k0 + 8);
            if (has2) computeO(acc, As, half, rxw, k0 + 4, wB);
        }
    }

#pragma unroll
    for (int i = 0; i < 8; i++) {
        float* wrow = &ws[(rxw + 4 * i) * OSTRIDE + colsub * 6];
        *(float2*)&wrow[0] = *(float2*)&acc[i][0];
        *(float2*)&wrow[2] = *(float2*)&acc[i][1];
        *(float2*)&wrow[4] = *(float2*)&acc[i][2];
    }
}

// ---------------------------------------------------------------------------
__device__ __forceinline__ float softplusf(float v)
{
    return (v > 15.f) ? v : log1pf(__expf(v));
}

// Rational-quadratic spline, register-only scratch. p = 47 raw params (smem).
__device__ void rqs_reg(const float* __restrict__ p,
                        float* __restrict__ xp, float* __restrict__ ldp)
{
    float x = *xp;
    bool inside = (x >= -TAILV) && (x <= TAILV);
    float xc = fminf(fmaxf(x, -TAILV), TAILV);

    float ew[NBINS], eh[NBINS];
    float mw = p[0], mh = p[16];
#pragma unroll
    for (int i = 1; i < NBINS; i++) { mw = fmaxf(mw, p[i]); mh = fmaxf(mh, p[16 + i]); }
    float Sw = 0.f, Sh = 0.f;
#pragma unroll
    for (int i = 0; i < NBINS; i++) {
        ew[i] = __expf(p[i] - mw);      Sw += ew[i];
        eh[i] = __expf(p[16 + i] - mh); Sh += eh[i];
    }
    float scw = (1.f - MINW * NBINS) / Sw;
    float sch = (1.f - MINH * NBINS) / Sh;

    int idx = 0;
    float cwlo = -TAILV, cwhi = TAILV;
    bool found = false;
    float cacc = 0.f;
#pragma unroll
    for (int i = 0; i < NBINS - 1; i++) {
        cacc += MINW + scw * ew[i];
        float cw = 6.f * cacc - 3.f;
        if (xc >= cw) { idx++; cwlo = cw; }
        else if (!found) { cwhi = cw; found = true; }
    }
    float chlo = -TAILV, chhi = TAILV;
    float hacc = 0.f;
#pragma unroll
    for (int i = 0; i < NBINS - 1; i++) {
        hacc += MINH + sch * eh[i];
        float ch = 6.f * hacc - 3.f;
        if (i == idx - 1) chlo = ch;
        if (i == idx)     chhi = ch;
    }

    float inw = cwhi - cwlo;
    float inh = chhi - chlo;
    float delta = inh / inw;
    float ind  = (idx == 0)          ? 1.f : MIND + softplusf(p[32 + idx - 1]);
    float ind1 = (idx == NBINS - 1)  ? 1.f : MIND + softplusf(p[32 + idx]);

    float th   = (xc - cwlo) / inw;
    float omt  = 1.f - th;
    float tomt = th * omt;
    float num  = inh * (delta * th * th + ind * tomt);
    float den  = delta + (ind + ind1 - 2.f * delta) * tomt;
    float y    = chlo + num / den;
    float dnum = delta * delta * (ind1 * th * th + 2.f * delta * tomt + ind * omt * omt);
    float lad  = __logf(dnum) - 2.f * __logf(den);

    *xp = inside ? y : x;
    if (inside) atomicAdd(ldp, lad);
}

// ---------------------------------------------------------------------------
__global__ void __launch_bounds__(NT, 3)
flow_kernel(const float* __restrict__ x_in,
            float* __restrict__ out, int batch)
{
    extern __shared__ float sm[];
    float* xs   = sm;                      // SPB * XL
    float* hbuf = xs + SPB * XL;           // SPB * TL
    float* tbuf = hbuf + SPB * TL;         // SPB * TL (also out-head scratch)
    float* ldv  = tbuf + SPB * TL;         // SPB

    int tid = threadIdx.x;
    int rx   = tid & 7;                    // row group (init/res): rows rx+8i
    int lane = tid & 31;
    int base = blockIdx.x * SPB;

    // Paired column assignment for init/residual GEMMs:
    const int w      = tid >> 5;
    const int colsub4 = (tid >> 3) & 3;
    const int c0lo = 16 * w + 4 * colsub4;
    const int c0hi = (112 - 16 * w) + 4 * colsub4;
    const int klres = kresg(2 * w + 1);
    const int khres = kresg(15 - 2 * w);

    // Out-head lane mapping + warp-private scratch (32*OSTRIDE floats/warp)
    const int rxw = lane >> 3;             // 0..3
    const int colsub = lane & 7;           // 0..7 (6 cols each)
    float* ws = tbuf + w * (32 * OSTRIDE);

    for (int i = tid; i < SPB * FF; i += NT) {
        int s = i / FF, f = i % FF;
        xs[s * XL + f] = x_in[(base + s) * FF + f];
    }
    for (int i = tid; i < SPB; i += NT) { xs[i * XL + FF] = 0.f; ldv[i] = 0.f; }
    __syncthreads();

    for (int l = 0; l < LL; l++) {
        // NO physical feature reversal: g_Wi is pre-flipped for even layers,
        // RQS writes to parity-mapped slots. (Exact: 12 flips = identity.)

        // h = xs @ Wi'^T + bi   (full k range 16: flip breaks early-exit)
        gemm2p<false, false>(xs, XL, g_Wi + l * 16 * HH, HH,
                             g_bi + l * HH, hbuf, TL,
                             rx, c0lo, c0hi, 16, 16);
        __syncthreads();

        const float* wr = g_Wr + l * 4 * HH * HH;
        const float* br = g_br + l * 4 * HH;

#pragma unroll
        for (int sub = 0; sub < 4; sub++) {
            const float* wt = wr + sub * HH * HH;
            const float* b = br + sub * HH;
            const float* src = (sub & 1) ? tbuf : hbuf;
            float* dst = (sub & 1) ? hbuf : tbuf;
            if (sub & 1)
                gemm2p<true, true>(src, TL, wt, HH, b, dst, TL,
                                   rx, c0lo, c0hi, klres, khres);
            else
                gemm2p<true, false>(src, TL, wt, HH, b, dst, TL,
                                    rx, c0lo, c0hi, klres, khres);
            __syncthreads();
        }

        // ---- out head: warp-autonomous, zero CTA barriers ----
        const float* wo = g_Wo + l * HH * OUTWP;
        const float* bo = g_bo + l * OUTWP;
        const int flip = ((l & 1) == 0);   // even layer: slot = 14 - f
#pragma unroll 1
        for (int q = 0; q < 4; q++) {
            int f = FEAT[w][q];
            if (f < 0) break;
            int kout = (f == 0) ? 0 : r4(cumcnt(f));
            int slot = flip ? (14 - f) : f;
            int c0w = f * FP + colsub * 6;
#pragma unroll 1
            for (int half = 0; half < 2; half++) {
                gemm_out(hbuf, wo, bo, ws, half, rxw, colsub, c0w, kout);
                __syncwarp();
                {
                    int s = 32 * half + lane;
                    rqs_reg(&ws[lane * OSTRIDE], &xs[s * XL + slot], &ldv[s]);
                }
                __syncwarp();
            }
        }
        __syncthreads();   // xs fully updated before next layer's init GEMM
    }

    for (int i = tid; i < SPB * FF; i += NT) {
        int s = i / FF, f = i % FF;
        out[(base + s) * FF + f] = xs[s * XL + f];
    }
    if (tid < SPB) out[batch * FF + base + tid] = ldv[tid];
}

static const int SMEM_BYTES = (SPB * XL + 2 * SPB * TL + SPB) * (int)sizeof(float);

extern "C" void kernel_launch(void* const* d_in, const int* in_sizes, int n_in,
                              void* d_out, int out_size)
{
    const float* x  = (const float*)d_in[0];
    const float* Wi = (const float*)d_in[1];
    const float* bi = (const float*)d_in[2];
    const float* Wr = (const float*)d_in[3];
    const float* br = (const float*)d_in[4];
    const float* Wo = (const float*)d_in[5];
    const float* bo = (const float*)d_in[6];
    float* out = (float*)d_out;

    int batch = in_sizes[0] / FF;

    cudaFuncSetAttribute(flow_kernel,
                         cudaFuncAttributeMaxDynamicSharedMemorySize, SMEM_BYTES);

    prep_kernel<<<2048, 256>>>(Wi, bi, Wr, br, Wo, bo);
    flow_kernel<<<batch / SPB, NT, SMEM_BYTES>>>(x, out, batch);
}

// round 16
// speedup vs baseline: 1.1569x; 1.1569x over previous
#include <cuda_runtime.h>
#include <math.h>

#define FF 15
#define HH 128
#define LL 12
#define NBINS 16
#define MM 47            // 3*NB - 1
#define OUTW (FF*MM)     // 705
#define FP 48            // padded per-feature width
#define NFP 16           // padded feature count
#define OUTWP (NFP*FP)   // 768
#define TAILV 3.0f
#define MINW 0.001f
#define MINH 0.001f
#define MIND 0.001f
#define SPB 64           // samples per block
#define TL 132           // row stride for h/t buffers
#define XL 16            // row stride for x buffer
#define NT 128           // threads per CTA
#define NROW 8           // rows per thread
#define RSTRIDE 8        // row-group count (row = rx + RSTRIDE*i)
#define OSTRIDE 54       // out-head warp-scratch row stride (EVEN: float2-safe)

typedef unsigned long long ull;

// Hidden units permuted sorted-by-degree (exact similarity transform).
__host__ __device__ __forceinline__ int cumcnt(int d)
{
    return (d <= 2) ? 10 * d : 9 * d + 2;
}
__host__ __device__ __forceinline__ int degnew(int j)
{
    return (j < 20) ? (j / 10 + 1) : ((j - 2) / 9 + 1);
}
__host__ __device__ __forceinline__ int permj(int j)
{
    int d = degnew(j);
    int t = j - cumcnt(d - 1);
    return (d - 1) + 14 * t;
}
__host__ __device__ __forceinline__ int r8(int x) { return (x + 7) & ~7; }
__host__ __device__ __forceinline__ int kresg(int g)
{
    return r8(cumcnt(degnew(8 * g + 7)));
}

// Balanced warp->features map for the out head (sum of kout ~equal per warp)
__device__ const signed char FEAT[4][4] = {
    {14, 9, 3, 0}, {13, 10, 4, -1}, {12, 11, 2, 1}, {8, 7, 6, 5}
};

// Pre-masked, transposed, permuted, padded weights (scratch)
// g_Wi: k-axis PRE-FLIPPED for even layers (virtual feature reversal)
__device__ float g_Wi[LL * 16 * HH];        // [l][k'(16)][j']
__device__ float g_Wr[LL * 4 * HH * HH];    // [l][blk*2+sub][k'][j']
__device__ float g_Wo[LL * HH * OUTWP];     // [l][k'][f*48+m]
__device__ float g_bo[LL * OUTWP];          // padded out bias
__device__ float g_bi[LL * HH];             // permuted init bias
__device__ float g_br[LL * 4 * HH];         // permuted res bias

// ---------------------------------------------------------------------------
__global__ void prep_kernel(const float* __restrict__ Wi,
                            const float* __restrict__ bi,
                            const float* __restrict__ Wr,
                            const float* __restrict__ br,
                            const float* __restrict__ Wo,
                            const float* __restrict__ bo)
{
    const int n1 = LL * 16 * HH;
    const int n2 = LL * 4 * HH * HH;
    const int n3 = LL * HH * OUTWP;
    const int n4 = LL * OUTWP;
    const int n5 = LL * HH;
    const int n6 = LL * 4 * HH;
    const int ntot = n1 + n2 + n3 + n4 + n5 + n6;
    for (int i = blockIdx.x * blockDim.x + threadIdx.x; i < ntot;
         i += gridDim.x * blockDim.x) {
        if (i < n1) {
            int j = i % HH;               // hidden (permuted) index
            int k = (i / HH) % 16;        // PHYSICAL xs slot
            int l = i / (16 * HH);
            // even layers: logical feature = 14-k (virtual reversal)
            int klog = ((l & 1) == 0) ? (14 - k) : k;
            float v = 0.f;
            if (klog >= 0 && klog < FF) {
                int oj = permj(j);
                if (degnew(j) >= klog + 1) v = Wi[(l * HH + oj) * FF + klog];
            }
            g_Wi[i] = v;
        } else if (i < n1 + n2) {
            int t = i - n1;
            int j = t % HH;
            int k = (t / HH) % HH;
            int m = t / (HH * HH);
            float v = 0.f;
            if (degnew(j) >= degnew(k))
                v = Wr[(m * HH + permj(j)) * HH + permj(k)];
            g_Wr[t] = v;
        } else if (i < n1 + n2 + n3) {
            int t = i - n1 - n2;
            int c = t % OUTWP;
            int k = (t / OUTWP) % HH;
            int l = t / (HH * OUTWP);
            int f = c / FP, m = c % FP;
            float v = 0.f;
            if (f < FF && m < MM) {
                if (f + 1 > degnew(k))
                    v = Wo[(l * OUTW + f * MM + m) * HH + permj(k)];
            }
            g_Wo[t] = v;
        } else if (i < n1 + n2 + n3 + n4) {
            int t = i - n1 - n2 - n3;
            int c = t % OUTWP;
            int l = t / OUTWP;
            int f = c / FP, m = c % FP;
            g_bo[t] = (f < FF && m < MM) ? bo[l * OUTW + f * MM + m] : 0.f;
        } else if (i < n1 + n2 + n3 + n4 + n5) {
            int t = i - n1 - n2 - n3 - n4;
            int j = t % HH;
            int l = t / HH;
            g_bi[t] = bi[l * HH + permj(j)];
        } else {
            int t = i - n1 - n2 - n3 - n4 - n5;
            int j = t % HH;
            int m = t / HH;
            g_br[t] = br[m * HH + permj(j)];
        }
    }
}

// ---------------------------------------------------------------------------
__device__ __forceinline__ void fma2(ull& d, ull a, ull b)
{
    asm("fma.rn.f32x2 %0, %1, %2, %0;" : "+l"(d) : "l"(a), "l"(b));
}
__device__ __forceinline__ ull pack2(float v)
{
    ull r; asm("mov.b64 %0, {%1, %1};" : "=l"(r) : "f"(v)); return r;
}
__device__ __forceinline__ ull packf2(float a, float b)
{
    ull r; asm("mov.b64 %0, {%1, %2};" : "=l"(r) : "f"(a), "f"(b)); return r;
}

// ---------------------------------------------------------------------------
// Paired GEMM (init/res): thread covers 4 low cols + 4 high cols.
// Loop1 (k < kl): all 8 cols. Loop2 (kl <= k < kh): high cols only.
// ---------------------------------------------------------------------------
template <bool RELU, bool ACC>
__device__ __forceinline__ void gemm2p(const float* __restrict__ As, int ald,
                                       const float* __restrict__ Wg, int wld,
                                       const float* __restrict__ bias,
                                       float* __restrict__ Cs, int cld,
                                       int rx, int c0lo, int c0hi,
                                       int kl, int kh)
{
    ull acc[NROW][4];
    {
        float2 b0 = *(const float2*)&bias[c0lo];
        float2 b1 = *(const float2*)&bias[c0lo + 2];
        float2 b2 = *(const float2*)&bias[c0hi];
        float2 b3 = *(const float2*)&bias[c0hi + 2];
#pragma unroll
        for (int i = 0; i < NROW; i++) {
            float2 p0 = make_float2(0.f, 0.f), p1 = p0, p2 = p0, p3 = p0;
            if (ACC) {
                const float* cr = &Cs[(rx + RSTRIDE * i) * cld];
                p0 = *(const float2*)&cr[c0lo];
                p1 = *(const float2*)&cr[c0lo + 2];
                p2 = *(const float2*)&cr[c0hi];
                p3 = *(const float2*)&cr[c0hi + 2];
            }
            acc[i][0] = packf2(b0.x + p0.x, b0.y + p0.y);
            acc[i][1] = packf2(b1.x + p1.x, b1.y + p1.y);
            acc[i][2] = packf2(b2.x + p2.x, b2.y + p2.y);
            acc[i][3] = packf2(b3.x + p3.x, b3.y + p3.y);
        }
    }

#pragma unroll 1
    for (int k0 = 0; k0 < kl; k0 += 4) {
        ull w[4][4];
#pragma unroll
        for (int kk = 0; kk < 4; kk++) {
            const float* wr = Wg + (k0 + kk) * wld;
            ulonglong2 lo = __ldg((const ulonglong2*)(wr + c0lo));
            ulonglong2 hi = __ldg((const ulonglong2*)(wr + c0hi));
            w[kk][0] = lo.x; w[kk][1] = lo.y;
            w[kk][2] = hi.x; w[kk][3] = hi.y;
        }
#pragma unroll
        for (int i = 0; i < NROW; i++) {
            float4 a = *(const float4*)&As[(rx + RSTRIDE * i) * ald + k0];
            if (RELU) {
                a.x = fmaxf(a.x, 0.f); a.y = fmaxf(a.y, 0.f);
                a.z = fmaxf(a.z, 0.f); a.w = fmaxf(a.w, 0.f);
            }
            ull a0 = pack2(a.x), a1 = pack2(a.y), a2 = pack2(a.z), a3 = pack2(a.w);
#pragma unroll
            for (int j = 0; j < 4; j++) fma2(acc[i][j], a0, w[0][j]);
#pragma unroll
            for (int j = 0; j < 4; j++) fma2(acc[i][j], a1, w[1][j]);
#pragma unroll
            for (int j = 0; j < 4; j++) fma2(acc[i][j], a2, w[2][j]);
#pragma unroll
            for (int j = 0; j < 4; j++) fma2(acc[i][j], a3, w[3][j]);
        }
    }

#pragma unroll 1
    for (int k0 = kl; k0 < kh; k0 += 4) {
        ull w[4][2];
#pragma unroll
        for (int kk = 0; kk < 4; kk++) {
            const float* wr = Wg + (k0 + kk) * wld;
            ulonglong2 hi = __ldg((const ulonglong2*)(wr + c0hi));
            w[kk][0] = hi.x; w[kk][1] = hi.y;
        }
#pragma unroll
        for (int i = 0; i < NROW; i++) {
            float4 a = *(const float4*)&As[(rx + RSTRIDE * i) * ald + k0];
            if (RELU) {
                a.x = fmaxf(a.x, 0.f); a.y = fmaxf(a.y, 0.f);
                a.z = fmaxf(a.z, 0.f); a.w = fmaxf(a.w, 0.f);
            }
            ull a0 = pack2(a.x), a1 = pack2(a.y), a2 = pack2(a.z), a3 = pack2(a.w);
            fma2(acc[i][2], a0, w[0][0]); fma2(acc[i][3], a0, w[0][1]);
            fma2(acc[i][2], a1, w[1][0]); fma2(acc[i][3], a1, w[1][1]);
            fma2(acc[i][2], a2, w[2][0]); fma2(acc[i][3], a2, w[2][1]);
            fma2(acc[i][2], a3, w[3][0]); fma2(acc[i][3], a3, w[3][1]);
        }
    }

#pragma unroll
    for (int i = 0; i < NROW; i++) {
        float* cr = &Cs[(rx + RSTRIDE * i) * cld];
        *(float2*)&cr[c0lo]     = *(float2*)&acc[i][0];
        *(float2*)&cr[c0lo + 2] = *(float2*)&acc[i][1];
        *(float2*)&cr[c0hi]     = *(float2*)&acc[i][2];
        *(float2*)&cr[c0hi + 2] = *(float2*)&acc[i][3];
    }
}

// ---------------------------------------------------------------------------
// Out-head GEMM for one (feature, 32-sample half), warp-private.
// Lane = rxw (lane>>3, 0..3) x colsub (lane&7, 6 cols each).
// Rows: 32*half + rxw + 4*i, i<8.  Writes ws[row_local*OSTRIDE + col].
// ---------------------------------------------------------------------------
__device__ __forceinline__ void gemm_out(const float* __restrict__ As,
                                         const float* __restrict__ Wg,
                                         const float* __restrict__ bias,
                                         float* __restrict__ ws,
                                         int half, int rxw, int colsub,
                                         int c0w, int kend)
{
    ull acc[8][3];
    {
        float2 b0 = *(const float2*)&bias[c0w];
        float2 b1 = *(const float2*)&bias[c0w + 2];
        float2 b2 = *(const float2*)&bias[c0w + 4];
#pragma unroll
        for (int i = 0; i < 8; i++) {
            acc[i][0] = packf2(b0.x, b0.y);
            acc[i][1] = packf2(b1.x, b1.y);
            acc[i][2] = packf2(b2.x, b2.y);
        }
    }

#pragma unroll 1
    for (int k0 = 0; k0 < kend; k0 += 4) {
        ull w[4][3];
#pragma unroll
        for (int kk = 0; kk < 4; kk++) {
            const float* wr = Wg + (k0 + kk) * OUTWP + c0w;
            w[kk][0] = __ldg((const ull*)(wr));
            w[kk][1] = __ldg((const ull*)(wr + 2));
            w[kk][2] = __ldg((const ull*)(wr + 4));
        }
#pragma unroll
        for (int i = 0; i < 8; i++) {
            float4 a = *(const float4*)&As[(32 * half + rxw + 4 * i) * TL + k0];
            ull a0 = pack2(a.x), a1 = pack2(a.y), a2 = pack2(a.z), a3 = pack2(a.w);
#pragma unroll
            for (int j = 0; j < 3; j++) fma2(acc[i][j], a0, w[0][j]);
#pragma unroll
            for (int j = 0; j < 3; j++) fma2(acc[i][j], a1, w[1][j]);
#pragma unroll
            for (int j = 0; j < 3; j++) fma2(acc[i][j], a2, w[2][j]);
#pragma unroll
            for (int j = 0; j < 3; j++) fma2(acc[i][j], a3, w[3][j]);
        }
    }

#pragma unroll
    for (int i = 0; i < 8; i++) {
        float* wrow = &ws[(rxw + 4 * i) * OSTRIDE + colsub * 6];
        *(float2*)&wrow[0] = *(float2*)&acc[i][0];
        *(float2*)&wrow[2] = *(float2*)&acc[i][1];
        *(float2*)&wrow[4] = *(float2*)&acc[i][2];
    }
}

// ---------------------------------------------------------------------------
__device__ __forceinline__ float softplusf(float v)
{
    return (v > 15.f) ? v : log1pf(__expf(v));
}

// Rational-quadratic spline, register-only scratch. p = 47 raw params (smem).
__device__ void rqs_reg(const float* __restrict__ p,
                        float* __restrict__ xp, float* __restrict__ ldp)
{
    float x = *xp;
    bool inside = (x >= -TAILV) && (x <= TAILV);
    float xc = fminf(fmaxf(x, -TAILV), TAILV);

    float ew[NBINS], eh[NBINS];
    float mw = p[0], mh = p[16];
#pragma unroll
    for (int i = 1; i < NBINS; i++) { mw = fmaxf(mw, p[i]); mh = fmaxf(mh, p[16 + i]); }
    float Sw = 0.f, Sh = 0.f;
#pragma unroll
    for (int i = 0; i < NBINS; i++) {
        ew[i] = __expf(p[i] - mw);      Sw += ew[i];
        eh[i] = __expf(p[16 + i] - mh); Sh += eh[i];
    }
    float scw = (1.f - MINW * NBINS) / Sw;
    float sch = (1.f - MINH * NBINS) / Sh;

    int idx = 0;
    float cwlo = -TAILV, cwhi = TAILV;
    bool found = false;
    float cacc = 0.f;
#pragma unroll
    for (int i = 0; i < NBINS - 1; i++) {
        cacc += MINW + scw * ew[i];
        float cw = 6.f * cacc - 3.f;
        if (xc >= cw) { idx++; cwlo = cw; }
        else if (!found) { cwhi = cw; found = true; }
    }
    float chlo = -TAILV, chhi = TAILV;
    float hacc = 0.f;
#pragma unroll
    for (int i = 0; i < NBINS - 1; i++) {
        hacc += MINH + sch * eh[i];
        float ch = 6.f * hacc - 3.f;
        if (i == idx - 1) chlo = ch;
        if (i == idx)     chhi = ch;
    }

    float inw = cwhi - cwlo;
    float inh = chhi - chlo;
    float delta = inh / inw;
    float ind  = (idx == 0)          ? 1.f : MIND + softplusf(p[32 + idx - 1]);
    float ind1 = (idx == NBINS - 1)  ? 1.f : MIND + softplusf(p[32 + idx]);

    float th   = (xc - cwlo) / inw;
    float omt  = 1.f - th;
    float tomt = th * omt;
    float num  = inh * (delta * th * th + ind * tomt);
    float den  = delta + (ind + ind1 - 2.f * delta) * tomt;
    float y    = chlo + num / den;
    float dnum = delta * delta * (ind1 * th * th + 2.f * delta * tomt + ind * omt * omt);
    float lad  = __logf(dnum) - 2.f * __logf(den);

    *xp = inside ? y : x;
    if (inside) atomicAdd(ldp, lad);
}

// ---------------------------------------------------------------------------
__global__ void __launch_bounds__(NT, 3)
flow_kernel(const float* __restrict__ x_in,
            float* __restrict__ out, int batch)
{
    extern __shared__ float sm[];
    float* xs   = sm;                      // SPB * XL
    float* hbuf = xs + SPB * XL;           // SPB * TL
    float* tbuf = hbuf + SPB * TL;         // SPB * TL (also out-head scratch)
    float* ldv  = tbuf + SPB * TL;         // SPB

    int tid = threadIdx.x;
    int rx   = tid & 7;                    // row group (init/res): rows rx+8i
    int lane = tid & 31;
    int base = blockIdx.x * SPB;

    // Paired column assignment for init/residual GEMMs (per R12):
    const int w      = tid >> 5;
    const int colsub4 = (tid >> 3) & 3;
    const int c0lo = 16 * w + 4 * colsub4;
    const int c0hi = (112 - 16 * w) + 4 * colsub4;
    const int klres = kresg(2 * w + 1);
    const int khres = kresg(15 - 2 * w);

    // Out-head lane mapping + warp-private scratch (32*OSTRIDE floats/warp)
    const int rxw = lane >> 3;             // 0..3
    const int colsub = lane & 7;           // 0..7 (6 cols each)
    float* ws = tbuf + w * (32 * OSTRIDE);

    for (int i = tid; i < SPB * FF; i += NT) {
        int s = i / FF, f = i % FF;
        xs[s * XL + f] = x_in[(base + s) * FF + f];
    }
    for (int i = tid; i < SPB; i += NT) { xs[i * XL + FF] = 0.f; ldv[i] = 0.f; }
    __syncthreads();

    for (int l = 0; l < LL; l++) {
        // NO physical feature reversal: g_Wi is pre-flipped for even layers,
        // RQS writes to parity-mapped slots. (12 flips = identity.)
        const int flip = ((l & 1) == 0);

        // h = xs @ Wi'^T + bi
        // odd layers: early-exit pairing (kl=8); even layers: flipped k-axis
        // breaks the low-k structure -> full range on all 8 cols (kl=16).
        gemm2p<false, false>(xs, XL, g_Wi + l * 16 * HH, HH,
                             g_bi + l * HH, hbuf, TL,
                             rx, c0lo, c0hi, flip ? 16 : 8, 16);
        __syncthreads();

        const float* wr = g_Wr + l * 4 * HH * HH;
        const float* br = g_br + l * 4 * HH;

#pragma unroll
        for (int sub = 0; sub < 4; sub++) {
            const float* wt = wr + sub * HH * HH;
            const float* b = br + sub * HH;
            const float* src = (sub & 1) ? tbuf : hbuf;
            float* dst = (sub & 1) ? hbuf : tbuf;
            if (sub & 1)
                gemm2p<true, true>(src, TL, wt, HH, b, dst, TL,
                                   rx, c0lo, c0hi, klres, khres);
            else
                gemm2p<true, false>(src, TL, wt, HH, b, dst, TL,
                                    rx, c0lo, c0hi, klres, khres);
            __syncthreads();
        }

        // ---- out head: warp-autonomous, zero CTA barriers ----
        const float* wo = g_Wo + l * HH * OUTWP;
        const float* bo = g_bo + l * OUTWP;
#pragma unroll 1
        for (int q = 0; q < 4; q++) {
            int f = FEAT[w][q];
            if (f < 0) break;
            int kout = (f == 0) ? 0 : r8(cumcnt(f));
            int slot = flip ? (14 - f) : f;
            int c0w = f * FP + colsub * 6;
#pragma unroll 1
            for (int half = 0; half < 2; half++) {
                gemm_out(hbuf, wo, bo, ws, half, rxw, colsub, c0w, kout);
                __syncwarp();
                {
                    int s = 32 * half + lane;
                    rqs_reg(&ws[lane * OSTRIDE], &xs[s * XL + slot], &ldv[s]);
                }
                __syncwarp();
            }
        }
        __syncthreads();   // xs fully updated before next layer's init GEMM
    }

    for (int i = tid; i < SPB * FF; i += NT) {
        int s = i / FF, f = i % FF;
        out[(base + s) * FF + f] = xs[s * XL + f];
    }
    if (tid < SPB) out[batch * FF + base + tid] = ldv[tid];
}

static const int SMEM_BYTES = (SPB * XL + 2 * SPB * TL + SPB) * (int)sizeof(float);

extern "C" void kernel_launch(void* const* d_in, const int* in_sizes, int n_in,
                              void* d_out, int out_size)
{
    const float* x  = (const float*)d_in[0];
    const float* Wi = (const float*)d_in[1];
    const float* bi = (const float*)d_in[2];
    const float* Wr = (const float*)d_in[3];
    const float* br = (const float*)d_in[4];
    const float* Wo = (const float*)d_in[5];
    const float* bo = (const float*)d_in[6];
    float* out = (float*)d_out;

    int batch = in_sizes[0] / FF;

    cudaFuncSetAttribute(flow_kernel,
                         cudaFuncAttributeMaxDynamicSharedMemorySize, SMEM_BYTES);

    prep_kernel<<<2048, 256>>>(Wi, bi, Wr, br, Wo, bo);
    flow_kernel<<<batch / SPB, NT, SMEM_BYTES>>>(x, out, batch);
}

// round 17
// speedup vs baseline: 1.2459x; 1.0770x over previous
#include <cuda_runtime.h>
#include <math.h>

#define FF 15
#define HH 128
#define LL 12
#define NBINS 16
#define MM 47            // 3*NB - 1
#define OUTW (FF*MM)     // 705
#define FP 48            // padded per-feature width
#define NFP 16           // padded feature count
#define OUTWP (NFP*FP)   // 768
#define TAILV 3.0f
#define MINW 0.001f
#define MINH 0.001f
#define MIND 0.001f
#define SPB 64           // samples per block
#define TL 132           // row stride for h/t buffers
#define XL 16            // row stride for x buffer
#define NT 128           // threads per CTA
#define NROW 8           // rows per thread
#define RSTRIDE 8        // row-group count (row = rx + RSTRIDE*i)
#define OSTRIDE 54       // out-head warp-scratch row stride (EVEN: float2-safe)

typedef unsigned long long ull;

// Hidden units permuted sorted-by-degree (exact similarity transform).
__host__ __device__ __forceinline__ int cumcnt(int d)
{
    return (d <= 2) ? 10 * d : 9 * d + 2;
}
__host__ __device__ __forceinline__ int degnew(int j)
{
    return (j < 20) ? (j / 10 + 1) : ((j - 2) / 9 + 1);
}
__host__ __device__ __forceinline__ int permj(int j)
{
    int d = degnew(j);
    int t = j - cumcnt(d - 1);
    return (d - 1) + 14 * t;
}
__host__ __device__ __forceinline__ int r8(int x) { return (x + 7) & ~7; }
__host__ __device__ __forceinline__ int kresg(int g)
{
    return r8(cumcnt(degnew(8 * g + 7)));
}

// Balanced warp->features map for the out head (sum of kout ~equal per warp)
__device__ const signed char FEAT[4][4] = {
    {14, 9, 3, 0}, {13, 10, 4, -1}, {12, 11, 2, 1}, {8, 7, 6, 5}
};

// Pre-masked, transposed, permuted, padded weights (scratch)
// g_Wi: k-axis PRE-FLIPPED for even layers (virtual feature reversal)
__device__ float g_Wi[LL * 16 * HH];        // [l][k'(16)][j']
__device__ float g_Wr[LL * 4 * HH * HH];    // [l][blk*2+sub][k'][j']
__device__ float g_Wo[LL * HH * OUTWP];     // [l][k'][f*48+m]
__device__ float g_bo[LL * OUTWP];          // padded out bias
__device__ float g_bi[LL * HH];             // permuted init bias
__device__ float g_br[LL * 4 * HH];         // permuted res bias

// ---------------------------------------------------------------------------
__global__ void prep_kernel(const float* __restrict__ Wi,
                            const float* __restrict__ bi,
                            const float* __restrict__ Wr,
                            const float* __restrict__ br,
                            const float* __restrict__ Wo,
                            const float* __restrict__ bo)
{
    const int n1 = LL * 16 * HH;
    const int n2 = LL * 4 * HH * HH;
    const int n3 = LL * HH * OUTWP;
    const int n4 = LL * OUTWP;
    const int n5 = LL * HH;
    const int n6 = LL * 4 * HH;
    const int ntot = n1 + n2 + n3 + n4 + n5 + n6;
    for (int i = blockIdx.x * blockDim.x + threadIdx.x; i < ntot;
         i += gridDim.x * blockDim.x) {
        if (i < n1) {
            int j = i % HH;               // hidden (permuted) index
            int k = (i / HH) % 16;        // PHYSICAL xs slot
            int l = i / (16 * HH);
            // even layers: logical feature = 14-k (virtual reversal)
            int klog = ((l & 1) == 0) ? (14 - k) : k;
            float v = 0.f;
            if (klog >= 0 && klog < FF) {
                int oj = permj(j);
                if (degnew(j) >= klog + 1) v = Wi[(l * HH + oj) * FF + klog];
            }
            g_Wi[i] = v;
        } else if (i < n1 + n2) {
            int t = i - n1;
            int j = t % HH;
            int k = (t / HH) % HH;
            int m = t / (HH * HH);
            float v = 0.f;
            if (degnew(j) >= degnew(k))
                v = Wr[(m * HH + permj(j)) * HH + permj(k)];
            g_Wr[t] = v;
        } else if (i < n1 + n2 + n3) {
            int t = i - n1 - n2;
            int c = t % OUTWP;
            int k = (t / OUTWP) % HH;
            int l = t / (HH * OUTWP);
            int f = c / FP, m = c % FP;
            float v = 0.f;
            if (f < FF && m < MM) {
                if (f + 1 > degnew(k))
                    v = Wo[(l * OUTW + f * MM + m) * HH + permj(k)];
            }
            g_Wo[t] = v;
        } else if (i < n1 + n2 + n3 + n4) {
            int t = i - n1 - n2 - n3;
            int c = t % OUTWP;
            int l = t / OUTWP;
            int f = c / FP, m = c % FP;
            g_bo[t] = (f < FF && m < MM) ? bo[l * OUTW + f * MM + m] : 0.f;
        } else if (i < n1 + n2 + n3 + n4 + n5) {
            int t = i - n1 - n2 - n3 - n4;
            int j = t % HH;
            int l = t / HH;
            g_bi[t] = bi[l * HH + permj(j)];
        } else {
            int t = i - n1 - n2 - n3 - n4 - n5;
            int j = t % HH;
            int m = t / HH;
            g_br[t] = br[m * HH + permj(j)];
        }
    }
}

// ---------------------------------------------------------------------------
__device__ __forceinline__ void fma2(ull& d, ull a, ull b)
{
    asm("fma.rn.f32x2 %0, %1, %2, %0;" : "+l"(d) : "l"(a), "l"(b));
}
__device__ __forceinline__ ull pack2(float v)
{
    ull r; asm("mov.b64 %0, {%1, %1};" : "=l"(r) : "f"(v)); return r;
}
__device__ __forceinline__ ull packf2(float a, float b)
{
    ull r; asm("mov.b64 %0, {%1, %2};" : "=l"(r) : "f"(a), "f"(b)); return r;
}

// ---------------------------------------------------------------------------
// Paired GEMM (init/res): thread covers 4 low cols + 4 high cols.
// Loop1 (k < kl): all 8 cols. Loop2 (kl <= k < kh): high cols only,
// unroll-2 (chunk counts are even for every warp -> exact, lets ptxas
// batch next-chunk LDGs behind current-chunk fma2s).
// ---------------------------------------------------------------------------
template <bool RELU, bool ACC>
__device__ __forceinline__ void gemm2p(const float* __restrict__ As, int ald,
                                       const float* __restrict__ Wg, int wld,
                                       const float* __restrict__ bias,
                                       float* __restrict__ Cs, int cld,
                                       int rx, int c0lo, int c0hi,
                                       int kl, int kh)
{
    ull acc[NROW][4];
    {
        float2 b0 = *(const float2*)&bias[c0lo];
        float2 b1 = *(const float2*)&bias[c0lo + 2];
        float2 b2 = *(const float2*)&bias[c0hi];
        float2 b3 = *(const float2*)&bias[c0hi + 2];
#pragma unroll
        for (int i = 0; i < NROW; i++) {
            float2 p0 = make_float2(0.f, 0.f), p1 = p0, p2 = p0, p3 = p0;
            if (ACC) {
                const float* cr = &Cs[(rx + RSTRIDE * i) * cld];
                p0 = *(const float2*)&cr[c0lo];
                p1 = *(const float2*)&cr[c0lo + 2];
                p2 = *(const float2*)&cr[c0hi];
                p3 = *(const float2*)&cr[c0hi + 2];
            }
            acc[i][0] = packf2(b0.x + p0.x, b0.y + p0.y);
            acc[i][1] = packf2(b1.x + p1.x, b1.y + p1.y);
            acc[i][2] = packf2(b2.x + p2.x, b2.y + p2.y);
            acc[i][3] = packf2(b3.x + p3.x, b3.y + p3.y);
        }
    }

#pragma unroll 1
    for (int k0 = 0; k0 < kl; k0 += 4) {
        ull w[4][4];
#pragma unroll
        for (int kk = 0; kk < 4; kk++) {
            const float* wr = Wg + (k0 + kk) * wld;
            ulonglong2 lo = __ldg((const ulonglong2*)(wr + c0lo));
            ulonglong2 hi = __ldg((const ulonglong2*)(wr + c0hi));
            w[kk][0] = lo.x; w[kk][1] = lo.y;
            w[kk][2] = hi.x; w[kk][3] = hi.y;
        }
#pragma unroll
        for (int i = 0; i < NROW; i++) {
            float4 a = *(const float4*)&As[(rx + RSTRIDE * i) * ald + k0];
            if (RELU) {
                a.x = fmaxf(a.x, 0.f); a.y = fmaxf(a.y, 0.f);
                a.z = fmaxf(a.z, 0.f); a.w = fmaxf(a.w, 0.f);
            }
            ull a0 = pack2(a.x), a1 = pack2(a.y), a2 = pack2(a.z), a3 = pack2(a.w);
#pragma unroll
            for (int j = 0; j < 4; j++) fma2(acc[i][j], a0, w[0][j]);
#pragma unroll
            for (int j = 0; j < 4; j++) fma2(acc[i][j], a1, w[1][j]);
#pragma unroll
            for (int j = 0; j < 4; j++) fma2(acc[i][j], a2, w[2][j]);
#pragma unroll
            for (int j = 0; j < 4; j++) fma2(acc[i][j], a3, w[3][j]);
        }
    }

#pragma unroll 2
    for (int k0 = kl; k0 < kh; k0 += 4) {
        ull w[4][2];
#pragma unroll
        for (int kk = 0; kk < 4; kk++) {
            const float* wr = Wg + (k0 + kk) * wld;
            ulonglong2 hi = __ldg((const ulonglong2*)(wr + c0hi));
            w[kk][0] = hi.x; w[kk][1] = hi.y;
        }
#pragma unroll
        for (int i = 0; i < NROW; i++) {
            float4 a = *(const float4*)&As[(rx + RSTRIDE * i) * ald + k0];
            if (RELU) {
                a.x = fmaxf(a.x, 0.f); a.y = fmaxf(a.y, 0.f);
                a.z = fmaxf(a.z, 0.f); a.w = fmaxf(a.w, 0.f);
            }
            ull a0 = pack2(a.x), a1 = pack2(a.y), a2 = pack2(a.z), a3 = pack2(a.w);
            fma2(acc[i][2], a0, w[0][0]); fma2(acc[i][3], a0, w[0][1]);
            fma2(acc[i][2], a1, w[1][0]); fma2(acc[i][3], a1, w[1][1]);
            fma2(acc[i][2], a2, w[2][0]); fma2(acc[i][3], a2, w[2][1]);
            fma2(acc[i][2], a3, w[3][0]); fma2(acc[i][3], a3, w[3][1]);
        }
    }

#pragma unroll
    for (int i = 0; i < NROW; i++) {
        float* cr = &Cs[(rx + RSTRIDE * i) * cld];
        *(float2*)&cr[c0lo]     = *(float2*)&acc[i][0];
        *(float2*)&cr[c0lo + 2] = *(float2*)&acc[i][1];
        *(float2*)&cr[c0hi]     = *(float2*)&acc[i][2];
        *(float2*)&cr[c0hi + 2] = *(float2*)&acc[i][3];
    }
}

// ---------------------------------------------------------------------------
// Out-head GEMM for one (feature, 32-sample half), warp-private.
// Lane = rxw (lane>>3, 0..3) x colsub (lane&7, 6 cols each).
// Rows: 32*half + rxw + 4*i, i<8.  Writes ws[row_local*OSTRIDE + col].
// k-loop unroll-2 (kout/4 even for all features) to prefetch next chunk.
// ---------------------------------------------------------------------------
__device__ __forceinline__ void gemm_out(const float* __restrict__ As,
                                         const float* __restrict__ Wg,
                                         const float* __restrict__ bias,
                                         float* __restrict__ ws,
                                         int half, int rxw, int colsub,
                                         int c0w, int kend)
{
    ull acc[8][3];
    {
        float2 b0 = *(const float2*)&bias[c0w];
        float2 b1 = *(const float2*)&bias[c0w + 2];
        float2 b2 = *(const float2*)&bias[c0w + 4];
#pragma unroll
        for (int i = 0; i < 8; i++) {
            acc[i][0] = packf2(b0.x, b0.y);
            acc[i][1] = packf2(b1.x, b1.y);
            acc[i][2] = packf2(b2.x, b2.y);
        }
    }

#pragma unroll 2
    for (int k0 = 0; k0 < kend; k0 += 4) {
        ull w[4][3];
#pragma unroll
        for (int kk = 0; kk < 4; kk++) {
            const float* wr = Wg + (k0 + kk) * OUTWP + c0w;
            w[kk][0] = __ldg((const ull*)(wr));
            w[kk][1] = __ldg((const ull*)(wr + 2));
            w[kk][2] = __ldg((const ull*)(wr + 4));
        }
#pragma unroll
        for (int i = 0; i < 8; i++) {
            float4 a = *(const float4*)&As[(32 * half + rxw + 4 * i) * TL + k0];
            ull a0 = pack2(a.x), a1 = pack2(a.y), a2 = pack2(a.z), a3 = pack2(a.w);
#pragma unroll
            for (int j = 0; j < 3; j++) fma2(acc[i][j], a0, w[0][j]);
#pragma unroll
            for (int j = 0; j < 3; j++) fma2(acc[i][j], a1, w[1][j]);
#pragma unroll
            for (int j = 0; j < 3; j++) fma2(acc[i][j], a2, w[2][j]);
#pragma unroll
            for (int j = 0; j < 3; j++) fma2(acc[i][j], a3, w[3][j]);
        }
    }

#pragma unroll
    for (int i = 0; i < 8; i++) {
        float* wrow = &ws[(rxw + 4 * i) * OSTRIDE + colsub * 6];
        *(float2*)&wrow[0] = *(float2*)&acc[i][0];
        *(float2*)&wrow[2] = *(float2*)&acc[i][1];
        *(float2*)&wrow[4] = *(float2*)&acc[i][2];
    }
}

// ---------------------------------------------------------------------------
__device__ __forceinline__ float softplusf(float v)
{
    return (v > 15.f) ? v : log1pf(__expf(v));
}

// Rational-quadratic spline, register-only scratch. p = 47 raw params (smem).
__device__ void rqs_reg(const float* __restrict__ p,
                        float* __restrict__ xp, float* __restrict__ ldp)
{
    float x = *xp;
    bool inside = (x >= -TAILV) && (x <= TAILV);
    float xc = fminf(fmaxf(x, -TAILV), TAILV);

    float ew[NBINS], eh[NBINS];
    float mw = p[0], mh = p[16];
#pragma unroll
    for (int i = 1; i < NBINS; i++) { mw = fmaxf(mw, p[i]); mh = fmaxf(mh, p[16 + i]); }
    float Sw = 0.f, Sh = 0.f;
#pragma unroll
    for (int i = 0; i < NBINS; i++) {
        ew[i] = __expf(p[i] - mw);      Sw += ew[i];
        eh[i] = __expf(p[16 + i] - mh); Sh += eh[i];
    }
    float scw = (1.f - MINW * NBINS) / Sw;
    float sch = (1.f - MINH * NBINS) / Sh;

    int idx = 0;
    float cwlo = -TAILV, cwhi = TAILV;
    bool found = false;
    float cacc = 0.f;
#pragma unroll
    for (int i = 0; i < NBINS - 1; i++) {
        cacc += MINW + scw * ew[i];
        float cw = 6.f * cacc - 3.f;
        if (xc >= cw) { idx++; cwlo = cw; }
        else if (!found) { cwhi = cw; found = true; }
    }
    float chlo = -TAILV, chhi = TAILV;
    float hacc = 0.f;
#pragma unroll
    for (int i = 0; i < NBINS - 1; i++) {
        hacc += MINH + sch * eh[i];
        float ch = 6.f * hacc - 3.f;
        if (i == idx - 1) chlo = ch;
        if (i == idx)     chhi = ch;
    }

    float inw = cwhi - cwlo;
    float inh = chhi - chlo;
    float delta = inh / inw;
    float ind  = (idx == 0)          ? 1.f : MIND + softplusf(p[32 + idx - 1]);
    float ind1 = (idx == NBINS - 1)  ? 1.f : MIND + softplusf(p[32 + idx]);

    float th   = (xc - cwlo) / inw;
    float omt  = 1.f - th;
    float tomt = th * omt;
    float num  = inh * (delta * th * th + ind * tomt);
    float den  = delta + (ind + ind1 - 2.f * delta) * tomt;
    float y    = chlo + num / den;
    float dnum = delta * delta * (ind1 * th * th + 2.f * delta * tomt + ind * omt * omt);
    float lad  = __logf(dnum) - 2.f * __logf(den);

    *xp = inside ? y : x;
    if (inside) atomicAdd(ldp, lad);
}

// ---------------------------------------------------------------------------
__global__ void __launch_bounds__(NT, 3)
flow_kernel(const float* __restrict__ x_in,
            float* __restrict__ out, int batch)
{
    extern __shared__ float sm[];
    float* xs   = sm;                      // SPB * XL
    float* hbuf = xs + SPB * XL;           // SPB * TL
    float* tbuf = hbuf + SPB * TL;         // SPB * TL (also out-head scratch)
    float* ldv  = tbuf + SPB * TL;         // SPB

    int tid = threadIdx.x;
    int rx   = tid & 7;                    // row group (init/res): rows rx+8i
    int lane = tid & 31;
    int base = blockIdx.x * SPB;

    // Paired column assignment for init/residual GEMMs (per R12):
    const int w      = tid >> 5;
    const int colsub4 = (tid >> 3) & 3;
    const int c0lo = 16 * w + 4 * colsub4;
    const int c0hi = (112 - 16 * w) + 4 * colsub4;
    const int klres = kresg(2 * w + 1);
    const int khres = kresg(15 - 2 * w);

    // Out-head lane mapping + warp-private scratch (32*OSTRIDE floats/warp)
    const int rxw = lane >> 3;             // 0..3
    const int colsub = lane & 7;           // 0..7 (6 cols each)
    float* ws = tbuf + w * (32 * OSTRIDE);

    for (int i = tid; i < SPB * FF; i += NT) {
        int s = i / FF, f = i % FF;
        xs[s * XL + f] = x_in[(base + s) * FF + f];
    }
    for (int i = tid; i < SPB; i += NT) { xs[i * XL + FF] = 0.f; ldv[i] = 0.f; }
    __syncthreads();

    for (int l = 0; l < LL; l++) {
        // NO physical feature reversal: g_Wi is pre-flipped for even layers,
        // RQS writes to parity-mapped slots. (12 flips = identity.)
        const int flip = ((l & 1) == 0);

        // h = xs @ Wi'^T + bi
        // odd layers: early-exit pairing (kl=8); even layers: flipped k-axis
        // breaks the low-k structure -> full range on all 8 cols (kl=16).
        gemm2p<false, false>(xs, XL, g_Wi + l * 16 * HH, HH,
                             g_bi + l * HH, hbuf, TL,
                             rx, c0lo, c0hi, flip ? 16 : 8, 16);
        __syncthreads();

        const float* wr = g_Wr + l * 4 * HH * HH;
        const float* br = g_br + l * 4 * HH;

#pragma unroll
        for (int sub = 0; sub < 4; sub++) {
            const float* wt = wr + sub * HH * HH;
            const float* b = br + sub * HH;
            const float* src = (sub & 1) ? tbuf : hbuf;
            float* dst = (sub & 1) ? hbuf : tbuf;
            if (sub & 1)
                gemm2p<true, true>(src, TL, wt, HH, b, dst, TL,
                                   rx, c0lo, c0hi, klres, khres);
            else
                gemm2p<true, false>(src, TL, wt, HH, b, dst, TL,
                                    rx, c0lo, c0hi, klres, khres);
            __syncthreads();
        }

        // ---- out head: warp-autonomous, zero CTA barriers ----
        const float* wo = g_Wo + l * HH * OUTWP;
        const float* bo = g_bo + l * OUTWP;
#pragma unroll 1
        for (int q = 0; q < 4; q++) {
            int f = FEAT[w][q];
            if (f < 0) break;
            int kout = (f == 0) ? 0 : r8(cumcnt(f));
            int slot = flip ? (14 - f) : f;
            int c0w = f * FP + colsub * 6;
#pragma unroll 1
            for (int half = 0; half < 2; half++) {
                gemm_out(hbuf, wo, bo, ws, half, rxw, colsub, c0w, kout);
                __syncwarp();
                {
                    int s = 32 * half + lane;
                    rqs_reg(&ws[lane * OSTRIDE], &xs[s * XL + slot], &ldv[s]);
                }
                __syncwarp();
            }
        }
        __syncthreads();   // xs fully updated before next layer's init GEMM
    }

    for (int i = tid; i < SPB * FF; i += NT) {
        int s = i / FF, f = i % FF;
        out[(base + s) * FF + f] = xs[s * XL + f];
    }
    if (tid < SPB) out[batch * FF + base + tid] = ldv[tid];
}

static const int SMEM_BYTES = (SPB * XL + 2 * SPB * TL + SPB) * (int)sizeof(float);

extern "C" void kernel_launch(void* const* d_in, const int* in_sizes, int n_in,
                              void* d_out, int out_size)
{
    const float* x  = (const float*)d_in[0];
    const float* Wi = (const float*)d_in[1];
    const float* bi = (const float*)d_in[2];
    const float* Wr = (const float*)d_in[3];
    const float* br = (const float*)d_in[4];
    const float* Wo = (const float*)d_in[5];
    const float* bo = (const float*)d_in[6];
    float* out = (float*)d_out;

    int batch = in_sizes[0] / FF;

    cudaFuncSetAttribute(flow_kernel,
                         cudaFuncAttributeMaxDynamicSharedMemorySize, SMEM_BYTES);

    prep_kernel<<<2048, 256>>>(Wi, bi, Wr, br, Wo, bo);
    flow_kernel<<<batch / SPB, NT, SMEM_BYTES>>>(x, out, batch);
}